// round 2
// baseline (speedup 1.0000x reference)
#include <cuda_runtime.h>
#include <cstdint>

#define BB 8
#define NN 16384
#define CC 80
#define TT 100
#define CAP 1536          // per-(b,c) candidate cap for band-0 filter (mean 819, sigma 28)
#define SORT_MAX 2048
#define PF 512            // boxes prefetched into smem for greedy loop

typedef unsigned long long ull;

// ---------------- scratch (static device globals; no allocation) ----------------
__device__ ull   g_cand[(size_t)BB * CC * CAP];     // ~7.9MB candidate keys
__device__ int   g_cnt[BB * CC];
__device__ float g_det_scores[BB * CC * TT];
__device__ float g_det_boxes[BB * CC * TT * 4];
__device__ int   g_det_cnt[BB * CC];

__device__ __forceinline__ ull make_cand_key(float s, int n) {
    return (((ull)(0xFFFFFFFFu - __float_as_uint(s))) << 32) | (unsigned)n;
}

// ---------------- kernel R: reset counters ----------------
__global__ void reset_kernel() {
    int i = blockIdx.x * blockDim.x + threadIdx.x;
    if (i < BB * CC) g_cnt[i] = 0;
}

// ---------------- kernel F: coalesced filter of scores >= 0.95 ----------------
__global__ __launch_bounds__(256) void filter_kernel(const float* __restrict__ scores) {
    unsigned i = blockIdx.x * 256u + threadIdx.x;      // over B*N*C = 10,485,760
    float s = scores[i];
    if (s >= 0.95f) {
        unsigned c = i % CC;
        unsigned bn = i / CC;
        unsigned b = bn >> 14;          // / NN
        unsigned n = bn & (NN - 1);
        int cls = (int)(b * CC + c);
        int slot = atomicAdd(&g_cnt[cls], 1);
        if (slot < CAP) g_cand[(size_t)cls * CAP + slot] = make_cand_key(s, (int)n);
    }
}

// ---------------- kernel 1: per (b,c) greedy NMS ----------------
__global__ __launch_bounds__(256) void nms_kernel(const float* __restrict__ boxes,
                                                  const float* __restrict__ scores) {
    const int c = blockIdx.x;
    const int b = blockIdx.y;
    const int tid = threadIdx.x;
    const int cls = b * CC + c;

    __shared__ ull keys[SORT_MAX];
    __shared__ float pb_y1[PF], pb_x1[PF], pb_y2[PF], pb_x2[PF], pb_ar[PF];
    __shared__ float acc_y1[TT], acc_x1[TT], acc_y2[TT], acc_x2[TT];
    __shared__ float acc_s[TT], acc_area[TT];
    __shared__ int s_cnt, s_accept;

    if (tid == 0) s_accept = 0;
    __syncthreads();

    int raw_cnt = g_cnt[cls];
    bool overflow = (raw_cnt > CAP);          // essentially impossible; handled by fallback
    int cnt = overflow ? 0 : raw_cnt;

    // ---- load band-0 candidates from the filter pass ----
    for (int i = tid; i < cnt; i += 256) keys[i] = g_cand[(size_t)cls * CAP + i];
    __syncthreads();

    // helper lambda-free macro-ish flow: we inline sort + greedy twice (band0 / fallback)
    if (cnt > 0) {
        // pad to pow2 + bitonic sort ascending (=> score desc, index asc)
        int m = 1; while (m < cnt) m <<= 1;
        for (int i = cnt + tid; i < m; i += 256) keys[i] = ~0ull;
        __syncthreads();
        for (int kk = 2; kk <= m; kk <<= 1)
            for (int j = kk >> 1; j > 0; j >>= 1) {
                for (int i = tid; i < m; i += 256) {
                    int ixj = i ^ j;
                    if (ixj > i) {
                        bool up = ((i & kk) == 0);
                        ull a = keys[i], bb2 = keys[ixj];
                        if ((a > bb2) == up) { keys[i] = bb2; keys[ixj] = a; }
                    }
                }
                __syncthreads();
            }

        // prefetch boxes for the first PF sorted candidates into smem
        int pf = cnt < PF ? cnt : PF;
        for (int i = tid; i < pf; i += 256) {
            int n = (int)(keys[i] & 0xFFFFFFFFu);
            float4 bx = __ldg(((const float4*)boxes) + ((size_t)b * NN + n));
            pb_y1[i] = bx.x; pb_x1[i] = bx.y; pb_y2[i] = bx.z; pb_x2[i] = bx.w;
            pb_ar[i] = fmaxf(bx.z - bx.x, 0.0f) * fmaxf(bx.w - bx.y, 0.0f);
        }
        __syncthreads();

        // serial greedy scan by warp 0; lanes parallelize accepted-box IoU checks
        if (tid < 32) {
            int lane = tid;
            int k = 0;
            for (int i = 0; i < cnt && k < TT; ++i) {
                ull key = keys[i];
                float y1, x1, y2, x2, ar;
                float sc = __uint_as_float(0xFFFFFFFFu - (unsigned)(key >> 32));
                if (i < pf) {
                    y1 = pb_y1[i]; x1 = pb_x1[i]; y2 = pb_y2[i]; x2 = pb_x2[i]; ar = pb_ar[i];
                } else {
                    int n = (int)(key & 0xFFFFFFFFu);
                    float4 bx = __ldg(((const float4*)boxes) + ((size_t)b * NN + n));
                    y1 = bx.x; x1 = bx.y; y2 = bx.z; x2 = bx.w;
                    ar = fmaxf(y2 - y1, 0.0f) * fmaxf(x2 - x1, 0.0f);
                }
                bool sup = false;
                for (int j = lane; j < k; j += 32) {
                    float yy1 = fmaxf(y1, acc_y1[j]);
                    float xx1 = fmaxf(x1, acc_x1[j]);
                    float yy2 = fminf(y2, acc_y2[j]);
                    float xx2 = fminf(x2, acc_x2[j]);
                    float inter = fmaxf(yy2 - yy1, 0.0f) * fmaxf(xx2 - xx1, 0.0f);
                    float uni = fmaxf(acc_area[j] + ar - inter, 1e-9f);
                    if (inter / uni >= 0.5f) sup = true;
                }
                if (!__any_sync(0xFFFFFFFFu, sup)) {
                    if (lane == 0) {
                        acc_y1[k] = y1; acc_x1[k] = x1; acc_y2[k] = y2; acc_x2[k] = x2;
                        acc_s[k] = sc; acc_area[k] = ar;
                    }
                    k++;
                    __syncwarp();
                }
            }
            if (lane == 0) s_accept = k;
            __syncwarp();
        }
        __syncthreads();
    }

    // ---- fallback bands below 0.95 (correctness only; never taken for this input) ----
    int band_start = overflow ? 0 : 1;
    for (int band = band_start; band < 14; ++band) {
        if (s_accept >= TT) break;
        const float lo = 0.95f - 0.05f * (float)band;
        const float hi = (band == 0) ? 1e30f : (0.95f - 0.05f * (float)(band - 1));
        if (tid == 0) s_cnt = 0;
        __syncthreads();
        for (int n = tid; n < NN; n += 256) {
            float s = scores[((size_t)b * NN + n) * CC + c];   // strided (fallback only)
            bool in = (band < 13) ? (s >= lo && s < hi) : (s > 0.3f && s < hi);
            if (in) {
                int p = atomicAdd(&s_cnt, 1);
                if (p < SORT_MAX) keys[p] = make_cand_key(s, n);
            }
        }
        __syncthreads();
        int bc = s_cnt; if (bc > SORT_MAX) bc = SORT_MAX;
        if (bc == 0) continue;
        int m = 1; while (m < bc) m <<= 1;
        for (int i = bc + tid; i < m; i += 256) keys[i] = ~0ull;
        __syncthreads();
        for (int kk = 2; kk <= m; kk <<= 1)
            for (int j = kk >> 1; j > 0; j >>= 1) {
                for (int i = tid; i < m; i += 256) {
                    int ixj = i ^ j;
                    if (ixj > i) {
                        bool up = ((i & kk) == 0);
                        ull a = keys[i], bb2 = keys[ixj];
                        if ((a > bb2) == up) { keys[i] = bb2; keys[ixj] = a; }
                    }
                }
                __syncthreads();
            }
        if (tid < 32) {
            int lane = tid;
            int k = s_accept;
            for (int i = 0; i < bc && k < TT; ++i) {
                ull key = keys[i];
                int n = (int)(key & 0xFFFFFFFFu);
                float sc = __uint_as_float(0xFFFFFFFFu - (unsigned)(key >> 32));
                float4 bx = __ldg(((const float4*)boxes) + ((size_t)b * NN + n));
                float ar = fmaxf(bx.z - bx.x, 0.0f) * fmaxf(bx.w - bx.y, 0.0f);
                bool sup = false;
                for (int j = lane; j < k; j += 32) {
                    float yy1 = fmaxf(bx.x, acc_y1[j]);
                    float xx1 = fmaxf(bx.y, acc_x1[j]);
                    float yy2 = fminf(bx.z, acc_y2[j]);
                    float xx2 = fminf(bx.w, acc_x2[j]);
                    float inter = fmaxf(yy2 - yy1, 0.0f) * fmaxf(xx2 - xx1, 0.0f);
                    float uni = fmaxf(acc_area[j] + ar - inter, 1e-9f);
                    if (inter / uni >= 0.5f) sup = true;
                }
                if (!__any_sync(0xFFFFFFFFu, sup)) {
                    if (lane == 0) {
                        acc_y1[k] = bx.x; acc_x1[k] = bx.y; acc_y2[k] = bx.z; acc_x2[k] = bx.w;
                        acc_s[k] = sc; acc_area[k] = ar;
                    }
                    k++;
                    __syncwarp();
                }
            }
            if (lane == 0) s_accept = k;
            __syncwarp();
        }
        __syncthreads();
    }

    // ---- write per-class results ----
    int k = s_accept;
    int base = cls * TT;
    if (tid == 0) g_det_cnt[cls] = k;
    for (int t = tid; t < k; t += 256) {
        g_det_scores[base + t] = acc_s[t];
        g_det_boxes[(base + t) * 4 + 0] = acc_y1[t];
        g_det_boxes[(base + t) * 4 + 1] = acc_x1[t];
        g_det_boxes[(base + t) * 4 + 2] = acc_y2[t];
        g_det_boxes[(base + t) * 4 + 3] = acc_x2[t];
    }
}

// ---------------- kernel 2: per-batch top-100 merge (single warp, reg-cached heads) --
__global__ __launch_bounds__(128) void merge_topk_kernel(float* __restrict__ out, int out_size) {
    const int b = blockIdx.x;
    const int tid = threadIdx.x;    // 128

    __shared__ float s_sc[CC * TT];     // 32KB
    __shared__ int s_cnt[CC];
    __shared__ int winners[TT];
    __shared__ int s_nv;

    const int OB = 0;
    const int OS = BB * TT * 4;
    const int OL = OS + BB * TT;
    const int OV = OL + BB * TT;

    // zero this batch's output slices (buffer is poisoned)
    for (int i = tid; i < TT * 4; i += 128) out[OB + (b * TT) * 4 + i] = 0.0f;
    for (int i = tid; i < TT; i += 128) { out[OS + b * TT + i] = 0.0f; out[OL + b * TT + i] = 0.0f; }
    if (tid == 0) out[OV + b] = 0.0f;

    // stage scores + counts + winner init
    for (int i = tid; i < CC * TT; i += 128) s_sc[i] = g_det_scores[b * CC * TT + i];
    if (tid < CC) s_cnt[tid] = g_det_cnt[b * CC + tid];
    for (int i = tid; i < TT; i += 128) winners[i] = -1;
    if (tid == 0) s_nv = 0;
    __syncthreads();

    if (tid < 32) {
        const int lane = tid;
        // lane owns classes lane, lane+32, lane+64; cache head keys in registers
        ull kk[3]; int hd[3];
        #pragma unroll
        for (int j = 0; j < 3; ++j) {
            int c = lane + 32 * j;
            hd[j] = 0;
            kk[j] = 0ull;
            if (c < CC && s_cnt[c] > 0) {
                unsigned fi = (unsigned)(c * TT);
                kk[j] = (((ull)__float_as_uint(s_sc[c * TT])) << 32) | (0xFFFFFFFFu - fi);
            }
        }
        int nv = 0;
        for (int t = 0; t < TT; ++t) {
            ull best = kk[0];
            if (kk[1] > best) best = kk[1];
            if (kk[2] > best) best = kk[2];
            #pragma unroll
            for (int off = 16; off > 0; off >>= 1) {
                ull o = __shfl_xor_sync(0xFFFFFFFFu, best, off);
                if (o > best) best = o;
            }
            if (best == 0ull) break;
            unsigned fi = 0xFFFFFFFFu - (unsigned)(best & 0xFFFFFFFFu);
            int c = (int)(fi / TT);
            int h = (int)(fi % TT);
            if (lane == 0) winners[t] = (int)fi;
            nv++;
            if ((c & 31) == lane) {
                int j = c >> 5;
                hd[j] = h + 1;
                kk[j] = 0ull;
                if (h + 1 < s_cnt[c]) {
                    unsigned nfi = (unsigned)(c * TT + h + 1);
                    kk[j] = (((ull)__float_as_uint(s_sc[c * TT + h + 1])) << 32)
                            | (0xFFFFFFFFu - nfi);
                }
            }
        }
        if (lane == 0) s_nv = nv;
    }
    __syncthreads();

    // parallel output epilogue
    for (int t = tid; t < TT; t += 128) {
        int fi = winners[t];
        if (fi < 0) continue;
        int c = fi / TT, h = fi % TT;
        int base = (b * CC + c) * TT + h;
        out[OS + b * TT + t] = g_det_scores[base];
        out[OL + b * TT + t] = (float)c;
        float4 bx = ((const float4*)g_det_boxes)[base];
        ((float4*)out)[(OB / 4) + b * TT + t] = bx;
    }
    if (tid == 0) out[OV + b] = (float)s_nv;
}

// ---------------- launch ----------------
extern "C" void kernel_launch(void* const* d_in, const int* in_sizes, int n_in,
                              void* d_out, int out_size) {
    const float* boxes  = (const float*)d_in[0];
    const float* scores = (const float*)d_in[1];
    if (n_in >= 2 && in_sizes[0] > in_sizes[1]) {
        const float* tmp = boxes; boxes = scores; scores = tmp;
    }
    float* out = (float*)d_out;

    reset_kernel<<<(BB * CC + 255) / 256, 256>>>();
    filter_kernel<<<(BB * NN * CC) / 256, 256>>>(scores);
    nms_kernel<<<dim3(CC, BB), 256>>>(boxes, scores);
    merge_topk_kernel<<<BB, 128>>>(out, out_size);
}